// round 12
// baseline (speedup 1.0000x reference)
#include <cuda_runtime.h>

#define BB 256
#define TT 512
#define EMBD 64
#define HID 128

// Transposed W_ih1, built once per launch: g_Wih1t[i*128+j] = float4(Wih1[j][4i..4i+3])
__device__ float4 g_Wih1t[16 * HID];

__global__ __launch_bounds__(128) void k_init(const float* __restrict__ Wih1)
{
    int i = blockIdx.x;        // 0..15  (k4 chunk)
    int j = threadIdx.x;       // 0..127 (feature)
    g_Wih1t[i * HID + j] = ((const float4*)Wih1)[j * 16 + i];
}

// ---------------------------------------------------------------------------
// ONE kernel: in-scan pre1 pipeline + R1's exact fused scan + fused epilogue.
// 128 CTAs x 256 threads; CTA handles batch rows b0, b0+1.
// Thread (j = tid&127, p = tid>>7) holds k-half rows of W_hh1/W_ih2/W_hh2.
// ---------------------------------------------------------------------------
__global__ __launch_bounds__(256, 1) void k_all(
    const int* __restrict__ x, const float* __restrict__ emb,
    const float* __restrict__ bih1, const float* __restrict__ bhh1,
    const float* __restrict__ Whh1,
    const float* __restrict__ Wih2, const float* __restrict__ bih2,
    const float* __restrict__ Whh2, const float* __restrict__ bhh2,
    const float* __restrict__ ln_g, const float* __restrict__ ln_b,
    const float* __restrict__ projW, const float* __restrict__ proj_b,
    const float* __restrict__ on_g, const float* __restrict__ on_b,
    float* __restrict__ out)
{
    __shared__ __align__(16) float sh_h1[2][HID];
    __shared__ __align__(16) float sh_h2[2][HID];
    __shared__ __align__(16) float sh_p[2][2][HID];    // [half][row][j]
    __shared__ __align__(16) float4 embR[8][2][16];    // emb ring [slot][row][c]
    __shared__ __align__(16) float preR[8][2][HID];    // pre1 ring [slot][row][j]
    __shared__ int xR[8][2];                           // token ring
    __shared__ float red[2][8];                        // epilogue reductions
    __shared__ __align__(16) float rep[2][HID];

    const int tid = threadIdx.x;
    const int j = tid & 127;
    const int p = tid >> 7;            // k-half / row role (warp-uniform)
    const int b0 = blockIdx.x * 2;

    // Scan weights in registers (k-half rows), exactly as R1.
    float W1r[64], Wi2r[64], W2r[64];
    {
        const float* w1 = Whh1 + j * HID + p * 64;
        const float* wi = Wih2 + j * HID + p * 64;
        const float* w2 = Whh2 + j * HID + p * 64;
#pragma unroll
        for (int i = 0; i < 64; ++i) { W1r[i] = w1[i]; Wi2r[i] = wi[i]; W2r[i] = w2[i]; }
    }
    const float bb1 = bih1[j] + bhh1[j];
    const float bb2 = bih2[j] + bhh2[j];

    sh_h1[p][j] = 0.f;
    sh_h2[p][j] = 0.f;
    __syncthreads();

    const float4* __restrict__ e4 = (const float4*)emb;
    const float4* h10p = (const float4*)&sh_h1[0][p * 64];
    const float4* h11p = (const float4*)&sh_h1[1][p * 64];
    const float4* g0p = (const float4*)&sh_h2[0][p * 64];
    const float4* g1p = (const float4*)&sh_h2[1][p * 64];

    int xv = 0;                 // pipeline carry: x token   (threads 0,1)
    float4 ev = {0, 0, 0, 0};   // pipeline carry: emb frag  (threads 0..31)

    for (int u = -8; u < TT; ++u) {
        // ======== pre1 software pipeline (phase-A region) ========
        if (tid < 2) {
            int t1 = u + 7;                       // S1: publish x token
            if (t1 >= 0 && t1 < TT) xR[t1 & 7][tid] = xv;
            int t0 = u + 8;                       // S0: issue next x load
            if (t0 < TT) xv = x[(b0 + tid) * TT + t0];
        }
        if (tid < 32) {
            int t3 = u + 5;                       // S3: publish emb frag
            if (t3 >= 0 && t3 < TT) embR[t3 & 7][tid >> 4][tid & 15] = ev;
            int t2 = u + 6;                       // S2: issue emb gather
            if (t2 >= 0 && t2 < TT) {
                int idx = xR[t2 & 7][tid >> 4];
                ev = e4[idx * 16 + (tid & 15)];
            }
        }
        {
            int t4 = u + 4;                       // S4: compute pre1(t4)
            if (t4 >= 0 && t4 < TT) {
                const float4* eb = &embR[t4 & 7][p][0];          // broadcast
                const float4* wt = g_Wih1t;                      // L1-resident
                float ac = bb1;
#pragma unroll
                for (int i = 0; i < 16; ++i) {
                    float4 e = eb[i];
                    float4 w = wt[i * HID + j];                  // coalesced
                    ac = fmaf(w.x, e.x, ac);
                    ac = fmaf(w.y, e.y, ac);
                    ac = fmaf(w.z, e.z, ac);
                    ac = fmaf(w.w, e.w, ac);
                }
                preR[t4 & 7][p][j] = ac;
            }
        }

        // ======== Phase A: W_hh1 * h1_old partials (both rows) ========
        if (u >= 0) {
            float a0 = 0.f, a1 = 0.f;
#pragma unroll
            for (int i = 0; i < 16; ++i) {
                float4 h0 = h10p[i];
                a0 = fmaf(W1r[4 * i + 0], h0.x, a0);
                a0 = fmaf(W1r[4 * i + 1], h0.y, a0);
                a0 = fmaf(W1r[4 * i + 2], h0.z, a0);
                a0 = fmaf(W1r[4 * i + 3], h0.w, a0);
                float4 h1 = h11p[i];
                a1 = fmaf(W1r[4 * i + 0], h1.x, a1);
                a1 = fmaf(W1r[4 * i + 1], h1.y, a1);
                a1 = fmaf(W1r[4 * i + 2], h1.z, a1);
                a1 = fmaf(W1r[4 * i + 3], h1.w, a1);
            }
            sh_p[p][0][j] = a0;
            sh_p[p][1][j] = a1;
        }
        __syncthreads();

        // ======== Phase B: h1_new = tanh(pre + sum) for row p ========
        if (u >= 0) {
            float v = preR[u & 7][p][j] + sh_p[0][p][j] + sh_p[1][p][j];
            sh_h1[p][j] = tanhf(v);
        }
        __syncthreads();

        // ======== Phase C: W_ih2*h1_new + W_hh2*h2_old partials ========
        if (u >= 0) {
            float c0 = 0.f, c1 = 0.f, d0 = 0.f, d1 = 0.f;
#pragma unroll
            for (int i = 0; i < 16; ++i) {
                float4 h0 = h10p[i];
                c0 = fmaf(Wi2r[4 * i + 0], h0.x, c0);
                c0 = fmaf(Wi2r[4 * i + 1], h0.y, c0);
                c0 = fmaf(Wi2r[4 * i + 2], h0.z, c0);
                c0 = fmaf(Wi2r[4 * i + 3], h0.w, c0);
                float4 h1 = h11p[i];
                c1 = fmaf(Wi2r[4 * i + 0], h1.x, c1);
                c1 = fmaf(Wi2r[4 * i + 1], h1.y, c1);
                c1 = fmaf(Wi2r[4 * i + 2], h1.z, c1);
                c1 = fmaf(Wi2r[4 * i + 3], h1.w, c1);
                float4 g0 = g0p[i];
                d0 = fmaf(W2r[4 * i + 0], g0.x, d0);
                d0 = fmaf(W2r[4 * i + 1], g0.y, d0);
                d0 = fmaf(W2r[4 * i + 2], g0.z, d0);
                d0 = fmaf(W2r[4 * i + 3], g0.w, d0);
                float4 g1 = g1p[i];
                d1 = fmaf(W2r[4 * i + 0], g1.x, d1);
                d1 = fmaf(W2r[4 * i + 1], g1.y, d1);
                d1 = fmaf(W2r[4 * i + 2], g1.z, d1);
                d1 = fmaf(W2r[4 * i + 3], g1.w, d1);
            }
            sh_p[p][0][j] = c0 + d0;
            sh_p[p][1][j] = c1 + d1;
        }
        __syncthreads();

        // ======== Phase D: h2_new = tanh(bb2 + sum) for row p ========
        if (u >= 0) {
            float v2 = bb2 + sh_p[0][p][j] + sh_p[1][p][j];
            sh_h2[p][j] = tanhf(v2);
        }
        __syncthreads();
    }

    // ======== Fused epilogue: LN -> proj -> tanh -> LN (row p) ========
    const int wg = (tid >> 5) & 3;     // warp index within the 128-thread group
    float v = sh_h2[p][j];

    float s = v, q = v * v;
#pragma unroll
    for (int o = 16; o; o >>= 1) {
        s += __shfl_xor_sync(0xffffffffu, s, o);
        q += __shfl_xor_sync(0xffffffffu, q, o);
    }
    if ((tid & 31) == 0) { red[p][wg] = s; red[p][4 + wg] = q; }
    __syncthreads();
    s = red[p][0] + red[p][1] + red[p][2] + red[p][3];
    q = red[p][4] + red[p][5] + red[p][6] + red[p][7];
    float mu = s * (1.f / HID);
    float var = q * (1.f / HID) - mu * mu;
    rep[p][j] = (v - mu) * rsqrtf(var + 1e-5f) * ln_g[j] + ln_b[j];
    __syncthreads();

    float acc = proj_b[j];
    {
        const float4* w4 = (const float4*)(projW + j * HID);
        const float4* r4 = (const float4*)&rep[p][0];
#pragma unroll
        for (int i = 0; i < 32; ++i) {
            float4 w = __ldg(&w4[i]);
            float4 r = r4[i];
            acc = fmaf(w.x, r.x, acc);
            acc = fmaf(w.y, r.y, acc);
            acc = fmaf(w.z, r.z, acc);
            acc = fmaf(w.w, r.w, acc);
        }
    }
    float tv = tanhf(acc);

    __syncthreads();   // red reuse
    s = tv; q = tv * tv;
#pragma unroll
    for (int o = 16; o; o >>= 1) {
        s += __shfl_xor_sync(0xffffffffu, s, o);
        q += __shfl_xor_sync(0xffffffffu, q, o);
    }
    if ((tid & 31) == 0) { red[p][wg] = s; red[p][4 + wg] = q; }
    __syncthreads();
    s = red[p][0] + red[p][1] + red[p][2] + red[p][3];
    q = red[p][4] + red[p][5] + red[p][6] + red[p][7];
    float mu2 = s * (1.f / HID);
    float var2 = q * (1.f / HID) - mu2 * mu2;
    out[(b0 + p) * HID + j] = (tv - mu2) * rsqrtf(var2 + 1e-5f) * on_g[j] + on_b[j];
}

// ---------------------------------------------------------------------------
extern "C" void kernel_launch(void* const* d_in, const int* in_sizes, int n_in,
                              void* d_out, int out_size)
{
    const int*   x     = (const int*)  d_in[0];
    const float* emb   = (const float*)d_in[1];
    const float* Wih1  = (const float*)d_in[2];
    const float* bih1  = (const float*)d_in[3];
    const float* Whh1  = (const float*)d_in[4];
    const float* bhh1  = (const float*)d_in[5];
    const float* Wih2  = (const float*)d_in[6];
    const float* bih2  = (const float*)d_in[7];
    const float* Whh2  = (const float*)d_in[8];
    const float* bhh2  = (const float*)d_in[9];
    const float* ln_g  = (const float*)d_in[10];
    const float* ln_b  = (const float*)d_in[11];
    const float* projW = (const float*)d_in[12];
    const float* projb = (const float*)d_in[13];
    const float* on_g  = (const float*)d_in[14];
    const float* on_b  = (const float*)d_in[15];

    k_init<<<16, 128>>>(Wih1);
    k_all<<<128, 256>>>(x, emb, bih1, bhh1, Whh1, Wih2, bih2, Whh2, bhh2,
                        ln_g, ln_b, projW, projb, on_g, on_b, (float*)d_out);
}